// round 2
// baseline (speedup 1.0000x reference)
#include <cuda_runtime.h>

// Problem constants (fixed by the dataset)
#define NMAX 50000
#define EMAX 640000

// Scratch (allocation-free rule: __device__ globals)
__device__ int   g_count[NMAX];           // in-degree counts (histogram)
__device__ float g_dinv[NMAX];            // deg (weighted, incl self) -> rsqrt in place
__device__ int   g_offsets[NMAX + 1];     // CSR row offsets (by dst)
__device__ int   g_cursor[NMAX];          // fill cursors
__device__ int   g_csr_src[EMAX];         // CSR column indices (src nodes)
__device__ float g_csr_norm[EMAX];        // per-edge normalization, CSR order
__device__ float g_h[NMAX * 128];         // GEMM output (pre-aggregation)
__device__ float g_agg[NMAX * 128];       // aggregation output
__device__ float g_h3[NMAX * 40];         // layer-3 GEMM output

// ---------------------------------------------------------------------------
// CSR build
// ---------------------------------------------------------------------------
__global__ void zero_kernel(int* count, float* deg, int n) {
    int i = blockIdx.x * blockDim.x + threadIdx.x;
    if (i < n) { count[i] = 0; deg[i] = 1.0f; }  // deg starts at self-loop weight
}

__global__ void hist_kernel(const int* __restrict__ dst,
                            const float* __restrict__ ew,
                            int* __restrict__ count,
                            float* __restrict__ deg, int e) {
    int i = blockIdx.x * blockDim.x + threadIdx.x;
    if (i < e) {
        int d = dst[i];
        atomicAdd(count + d, 1);
        atomicAdd(deg + d, ew[i]);
    }
}

// Single-block exclusive scan of count[n] -> offsets/cursor; also deg -> dinv.
__global__ void __launch_bounds__(1024)
scan_kernel(const int* __restrict__ count,
            float* __restrict__ deg_dinv,
            int* __restrict__ offsets,
            int* __restrict__ cursor, int n) {
    __shared__ int part[1024];
    const int t = threadIdx.x;
    const int C = (n + 1023) / 1024;   // 49 for n=50000
    const int base = t * C;

    int sum = 0;
    for (int i = 0; i < C; i++) {
        int idx = base + i;
        sum += (idx < n) ? count[idx] : 0;
    }
    part[t] = sum;
    __syncthreads();
    // inclusive scan over partials
    for (int off = 1; off < 1024; off <<= 1) {
        int v = (t >= off) ? part[t - off] : 0;
        __syncthreads();
        part[t] += v;
        __syncthreads();
    }
    int run = (t > 0) ? part[t - 1] : 0;
    for (int i = 0; i < C; i++) {
        int idx = base + i;
        if (idx < n) {
            offsets[idx] = run;
            cursor[idx] = run;
            run += count[idx];
        }
    }
    if (t == 1023) offsets[n] = part[1023];

    // dinv = rsqrt(deg), deg >= 1 always (self-loop)
    for (int i = t; i < n; i += 1024) deg_dinv[i] = rsqrtf(deg_dinv[i]);
}

__global__ void fill_kernel(const int* __restrict__ src,
                            const int* __restrict__ dst,
                            const float* __restrict__ ew,
                            const float* __restrict__ dinv,
                            int* __restrict__ cursor,
                            int* __restrict__ csr_src,
                            float* __restrict__ csr_norm, int e) {
    int i = blockIdx.x * blockDim.x + threadIdx.x;
    if (i >= e) return;
    int s = src[i];
    int d = dst[i];
    int pos = atomicAdd(cursor + d, 1);
    csr_src[pos] = s;
    csr_norm[pos] = dinv[s] * ew[i] * dinv[d];
}

// ---------------------------------------------------------------------------
// GEMM: [n,128] @ [128,128] -> H only. Optional ReLU on the A operand.
// BM=128, BN=128, BK=16, 256 threads, 8x8 microtile.
// ---------------------------------------------------------------------------
template <bool RELU_IN>
__global__ void __launch_bounds__(256, 2)
gemm128_kernel(const float* __restrict__ A,
               const float* __restrict__ W,
               float* __restrict__ Hout,
               int n) {
    __shared__ float As[16][128];  // transposed: As[k][m]
    __shared__ float Bs[16][128];  // Bs[k][n]

    const int tid = threadIdx.x;
    const int tx = tid & 15;        // N dim
    const int ty = tid >> 4;        // M dim
    const int rb = blockIdx.x * 128;

    float acc[8][8];
#pragma unroll
    for (int i = 0; i < 8; i++)
#pragma unroll
        for (int j = 0; j < 8; j++) acc[i][j] = 0.0f;

    for (int k0 = 0; k0 < 128; k0 += 16) {
#pragma unroll
        for (int l = 0; l < 2; l++) {
            int f = tid + l * 256;
            int row = f >> 2;
            int c4 = (f & 3) * 4;
            float4 v = make_float4(0.f, 0.f, 0.f, 0.f);
            int gr = rb + row;
            if (gr < n) v = *(const float4*)(A + (size_t)gr * 128 + k0 + c4);
            if (RELU_IN) {
                v.x = fmaxf(v.x, 0.f); v.y = fmaxf(v.y, 0.f);
                v.z = fmaxf(v.z, 0.f); v.w = fmaxf(v.w, 0.f);
            }
            As[c4 + 0][row] = v.x;
            As[c4 + 1][row] = v.y;
            As[c4 + 2][row] = v.z;
            As[c4 + 3][row] = v.w;
        }
#pragma unroll
        for (int l = 0; l < 2; l++) {
            int f = tid + l * 256;
            int kr = f >> 5;
            int c = (f & 31) * 4;
            float4 v = *(const float4*)(W + (size_t)(k0 + kr) * 128 + c);
            *(float4*)&Bs[kr][c] = v;
        }
        __syncthreads();

#pragma unroll
        for (int k = 0; k < 16; k++) {
            float4 a0 = *(const float4*)&As[k][ty * 8];
            float4 a1 = *(const float4*)&As[k][ty * 8 + 4];
            float4 b0 = *(const float4*)&Bs[k][tx * 8];
            float4 b1 = *(const float4*)&Bs[k][tx * 8 + 4];
            float a[8] = {a0.x, a0.y, a0.z, a0.w, a1.x, a1.y, a1.z, a1.w};
            float b[8] = {b0.x, b0.y, b0.z, b0.w, b1.x, b1.y, b1.z, b1.w};
#pragma unroll
            for (int i = 0; i < 8; i++)
#pragma unroll
                for (int j = 0; j < 8; j++)
                    acc[i][j] = fmaf(a[i], b[j], acc[i][j]);
        }
        __syncthreads();
    }

#pragma unroll
    for (int i = 0; i < 8; i++) {
        int row = rb + ty * 8 + i;
        if (row >= n) break;
#pragma unroll
        for (int j = 0; j < 8; j += 4) {
            int col = tx * 8 + j;
            float4 hv = make_float4(acc[i][j], acc[i][j + 1], acc[i][j + 2], acc[i][j + 3]);
            *(float4*)(Hout + (size_t)row * 128 + col) = hv;
        }
    }
}

// ---------------------------------------------------------------------------
// CSR gather (128 features): one warp per destination node.
// out[v] = h[v]*dinv[v]^2 + bias + sum_{e in in(v)} h[src(e)] * norm(e)
// ---------------------------------------------------------------------------
__global__ void __launch_bounds__(256)
gather128_kernel(const float* __restrict__ h,
                 const int* __restrict__ csr_src,
                 const float* __restrict__ csr_norm,
                 const int* __restrict__ offsets,
                 const float* __restrict__ dinv,
                 const float* __restrict__ bias,
                 float* __restrict__ out, int n) {
    int v = (blockIdx.x * blockDim.x + threadIdx.x) >> 5;
    int lane = threadIdx.x & 31;
    if (v >= n) return;

    int beg = offsets[v];
    int end = offsets[v + 1];
    float di = dinv[v];
    di *= di;

    float4 hv = *(const float4*)(h + (size_t)v * 128 + lane * 4);
    float4 bv = *(const float4*)(bias + lane * 4);
    float4 acc;
    acc.x = fmaf(hv.x, di, bv.x);
    acc.y = fmaf(hv.y, di, bv.y);
    acc.z = fmaf(hv.z, di, bv.z);
    acc.w = fmaf(hv.w, di, bv.w);

    int j = beg;
    for (; j + 4 <= end; j += 4) {
        int s0 = csr_src[j], s1 = csr_src[j + 1], s2 = csr_src[j + 2], s3 = csr_src[j + 3];
        float n0 = csr_norm[j], n1 = csr_norm[j + 1], n2 = csr_norm[j + 2], n3 = csr_norm[j + 3];
        float4 v0 = *(const float4*)(h + (size_t)s0 * 128 + lane * 4);
        float4 v1 = *(const float4*)(h + (size_t)s1 * 128 + lane * 4);
        float4 v2 = *(const float4*)(h + (size_t)s2 * 128 + lane * 4);
        float4 v3 = *(const float4*)(h + (size_t)s3 * 128 + lane * 4);
        acc.x += v0.x * n0 + v1.x * n1 + v2.x * n2 + v3.x * n3;
        acc.y += v0.y * n0 + v1.y * n1 + v2.y * n2 + v3.y * n3;
        acc.z += v0.z * n0 + v1.z * n1 + v2.z * n2 + v3.z * n3;
        acc.w += v0.w * n0 + v1.w * n1 + v2.w * n2 + v3.w * n3;
    }
    for (; j < end; j++) {
        int s = csr_src[j];
        float nm = csr_norm[j];
        float4 v0 = *(const float4*)(h + (size_t)s * 128 + lane * 4);
        acc.x = fmaf(v0.x, nm, acc.x);
        acc.y = fmaf(v0.y, nm, acc.y);
        acc.z = fmaf(v0.z, nm, acc.z);
        acc.w = fmaf(v0.w, nm, acc.w);
    }
    *(float4*)(out + (size_t)v * 128 + lane * 4) = acc;
}

// ---------------------------------------------------------------------------
// Layer-3 GEMM: [n,128] @ [128,40] -> H3 only. ReLU on A load.
// ---------------------------------------------------------------------------
__global__ void __launch_bounds__(128)
gemm40_kernel(const float* __restrict__ A,
              const float* __restrict__ W,
              float* __restrict__ Hout, int n) {
    extern __shared__ float sm[];
    float* xs = sm;                 // 64 rows, stride 129
    float* ws = sm + 64 * 129;      // 128*40 flat

    const int tid = threadIdx.x;
    const int rb = blockIdx.x * 64;

    for (int l = tid * 4; l < 128 * 40; l += 128 * 4)
        *(float4*)(ws + l) = *(const float4*)(W + l);

    for (int f = tid; f < 2048; f += 128) {
        int row = f >> 5;
        int c = (f & 31) * 4;
        float4 v = make_float4(0.f, 0.f, 0.f, 0.f);
        int gr = rb + row;
        if (gr < n) v = *(const float4*)(A + (size_t)gr * 128 + c);
        float* xr = xs + row * 129 + c;
        xr[0] = fmaxf(v.x, 0.f);
        xr[1] = fmaxf(v.y, 0.f);
        xr[2] = fmaxf(v.z, 0.f);
        xr[3] = fmaxf(v.w, 0.f);
    }
    __syncthreads();

    const int tc = tid & 7;
    const int tr = tid >> 3;
    float acc[4][5];
#pragma unroll
    for (int r = 0; r < 4; r++)
#pragma unroll
        for (int j = 0; j < 5; j++) acc[r][j] = 0.0f;

#pragma unroll 4
    for (int k = 0; k < 128; k++) {
        float w[5];
#pragma unroll
        for (int j = 0; j < 5; j++) w[j] = ws[k * 40 + tc + 8 * j];
#pragma unroll
        for (int r = 0; r < 4; r++) {
            float a = xs[(tr * 4 + r) * 129 + k];
#pragma unroll
            for (int j = 0; j < 5; j++) acc[r][j] = fmaf(a, w[j], acc[r][j]);
        }
    }

#pragma unroll
    for (int r = 0; r < 4; r++) {
        int row = rb + tr * 4 + r;
        if (row >= n) break;
#pragma unroll
        for (int j = 0; j < 5; j++)
            Hout[(size_t)row * 40 + tc + 8 * j] = acc[r][j];
    }
}

// ---------------------------------------------------------------------------
// CSR gather (40 features): one warp per node, lanes 0..9 hold one float4 each
// ---------------------------------------------------------------------------
__global__ void __launch_bounds__(256)
gather40_kernel(const float* __restrict__ h,
                const int* __restrict__ csr_src,
                const float* __restrict__ csr_norm,
                const int* __restrict__ offsets,
                const float* __restrict__ dinv,
                const float* __restrict__ bias,
                float* __restrict__ out, int n) {
    int v = (blockIdx.x * blockDim.x + threadIdx.x) >> 5;
    int lane = threadIdx.x & 31;
    if (v >= n) return;

    int beg = offsets[v];
    int end = offsets[v + 1];

    if (lane < 10) {
        float di = dinv[v];
        di *= di;
        float4 hv = *(const float4*)(h + (size_t)v * 40 + lane * 4);
        float4 bv = *(const float4*)(bias + lane * 4);
        float4 acc;
        acc.x = fmaf(hv.x, di, bv.x);
        acc.y = fmaf(hv.y, di, bv.y);
        acc.z = fmaf(hv.z, di, bv.z);
        acc.w = fmaf(hv.w, di, bv.w);

        int j = beg;
        for (; j + 4 <= end; j += 4) {
            int s0 = csr_src[j], s1 = csr_src[j + 1], s2 = csr_src[j + 2], s3 = csr_src[j + 3];
            float n0 = csr_norm[j], n1 = csr_norm[j + 1], n2 = csr_norm[j + 2], n3 = csr_norm[j + 3];
            float4 v0 = *(const float4*)(h + (size_t)s0 * 40 + lane * 4);
            float4 v1 = *(const float4*)(h + (size_t)s1 * 40 + lane * 4);
            float4 v2 = *(const float4*)(h + (size_t)s2 * 40 + lane * 4);
            float4 v3 = *(const float4*)(h + (size_t)s3 * 40 + lane * 4);
            acc.x += v0.x * n0 + v1.x * n1 + v2.x * n2 + v3.x * n3;
            acc.y += v0.y * n0 + v1.y * n1 + v2.y * n2 + v3.y * n3;
            acc.z += v0.z * n0 + v1.z * n1 + v2.z * n2 + v3.z * n3;
            acc.w += v0.w * n0 + v1.w * n1 + v2.w * n2 + v3.w * n3;
        }
        for (; j < end; j++) {
            int s = csr_src[j];
            float nm = csr_norm[j];
            float4 v0 = *(const float4*)(h + (size_t)s * 40 + lane * 4);
            acc.x = fmaf(v0.x, nm, acc.x);
            acc.y = fmaf(v0.y, nm, acc.y);
            acc.z = fmaf(v0.z, nm, acc.z);
            acc.w = fmaf(v0.w, nm, acc.w);
        }
        *(float4*)(out + (size_t)v * 40 + lane * 4) = acc;
    }
}

// ---------------------------------------------------------------------------
// Launch
// ---------------------------------------------------------------------------
extern "C" void kernel_launch(void* const* d_in, const int* in_sizes, int n_in,
                              void* d_out, int out_size) {
    const float* x  = (const float*)d_in[0];
    const int*   ei = (const int*)d_in[1];
    const float* ew = (const float*)d_in[2];
    const float* W1 = (const float*)d_in[3];
    const float* b1 = (const float*)d_in[4];
    const float* W2 = (const float*)d_in[5];
    const float* b2 = (const float*)d_in[6];
    const float* W3 = (const float*)d_in[7];
    const float* b3 = (const float*)d_in[8];
    float* out = (float*)d_out;

    const int n = in_sizes[0] / 128;       // 50000
    const int e = in_sizes[2];             // 640000
    const int* src = ei;
    const int* dst = ei + e;

    int *count, *offsets, *cursor, *csr_src;
    float *dinv, *csr_norm, *h, *agg, *h3;
    cudaGetSymbolAddress((void**)&count,    g_count);
    cudaGetSymbolAddress((void**)&dinv,     g_dinv);
    cudaGetSymbolAddress((void**)&offsets,  g_offsets);
    cudaGetSymbolAddress((void**)&cursor,   g_cursor);
    cudaGetSymbolAddress((void**)&csr_src,  g_csr_src);
    cudaGetSymbolAddress((void**)&csr_norm, g_csr_norm);
    cudaGetSymbolAddress((void**)&h,        g_h);
    cudaGetSymbolAddress((void**)&agg,      g_agg);
    cudaGetSymbolAddress((void**)&h3,       g_h3);

    const int nb_n = (n + 255) / 256;
    const int nb_e = (e + 255) / 256;

    // CSR build
    zero_kernel<<<nb_n, 256>>>(count, dinv, n);
    hist_kernel<<<nb_e, 256>>>(dst, ew, count, dinv, e);
    scan_kernel<<<1, 1024>>>(count, dinv, offsets, cursor, n);
    fill_kernel<<<nb_e, 256>>>(src, dst, ew, dinv, cursor, csr_src, csr_norm, e);

    const int gemm_blocks = (n + 127) / 128;
    const int gath_blocks = (n * 32 + 255) / 256;   // one warp per node

    // Layer 1
    gemm128_kernel<false><<<gemm_blocks, 256>>>(x, W1, h, n);
    gather128_kernel<<<gath_blocks, 256>>>(h, csr_src, csr_norm, offsets, dinv, b1, agg, n);

    // Layer 2 (relu fused into GEMM A-load)
    gemm128_kernel<true><<<gemm_blocks, 256>>>(agg, W2, h, n);
    gather128_kernel<<<gath_blocks, 256>>>(h, csr_src, csr_norm, offsets, dinv, b2, agg, n);

    // Layer 3
    static const int g40_smem = (64 * 129 + 128 * 40) * sizeof(float);
    cudaFuncSetAttribute(gemm40_kernel,
                         cudaFuncAttributeMaxDynamicSharedMemorySize, g40_smem);
    gemm40_kernel<<<(n + 63) / 64, 128, g40_smem>>>(agg, W3, h3, n);
    gather40_kernel<<<gath_blocks, 256>>>(h3, csr_src, csr_norm, offsets, dinv, b3, out, n);
}

// round 3
// speedup vs baseline: 1.1330x; 1.1330x over previous
#include <cuda_runtime.h>

// Problem constants (fixed by the dataset)
#define NMAX 50000
#define EMAX 640000

// Scratch (__device__ globals; no allocation allowed)
__device__ int   g_count[NMAX];           // out-degree counts (by src)
__device__ float g_dinv[NMAX];            // weighted in-degree (incl self) -> rsqrt
__device__ int   g_offsets[NMAX + 1];     // CSR row offsets (by src)
__device__ int   g_cursor[NMAX];          // fill cursors
__device__ int2  g_csr[EMAX];             // payload: {dst, __float_as_int(norm)}
__device__ float g_agg1[NMAX * 128];      // layer-1 aggregation output
__device__ float g_agg2[NMAX * 128];      // layer-2 aggregation output

__device__ __forceinline__ void red4(float* p, float a, float b, float c, float d) {
    asm volatile("red.global.add.v4.f32 [%0], {%1, %2, %3, %4};"
                 :: "l"(p), "f"(a), "f"(b), "f"(c), "f"(d) : "memory");
}

// ---------------------------------------------------------------------------
// CSR build (by src) + degree normalization (by dst)
// ---------------------------------------------------------------------------
__global__ void zero_kernel(int* count, float* deg, int n) {
    int i = blockIdx.x * blockDim.x + threadIdx.x;
    if (i < n) { count[i] = 0; deg[i] = 1.0f; }  // self-loop weight
}

__global__ void hist_kernel(const int* __restrict__ src,
                            const int* __restrict__ dst,
                            const float* __restrict__ ew,
                            int* __restrict__ count,
                            float* __restrict__ deg, int e) {
    int i = blockIdx.x * blockDim.x + threadIdx.x;
    if (i < e) {
        atomicAdd(count + src[i], 1);
        atomicAdd(deg + dst[i], ew[i]);
    }
}

// Single-block exclusive scan of count[n] -> offsets/cursor; deg -> rsqrt(deg).
__global__ void __launch_bounds__(1024)
scan_kernel(const int* __restrict__ count,
            float* __restrict__ deg_dinv,
            int* __restrict__ offsets,
            int* __restrict__ cursor, int n) {
    __shared__ int part[1024];
    const int t = threadIdx.x;
    const int C = (n + 1023) / 1024;
    const int base = t * C;

    int sum = 0;
    for (int i = 0; i < C; i++) {
        int idx = base + i;
        sum += (idx < n) ? count[idx] : 0;
    }
    part[t] = sum;
    __syncthreads();
    for (int off = 1; off < 1024; off <<= 1) {
        int v = (t >= off) ? part[t - off] : 0;
        __syncthreads();
        part[t] += v;
        __syncthreads();
    }
    int run = (t > 0) ? part[t - 1] : 0;
    for (int i = 0; i < C; i++) {
        int idx = base + i;
        if (idx < n) {
            offsets[idx] = run;
            cursor[idx] = run;
            run += count[idx];
        }
    }
    if (t == 1023) offsets[n] = part[1023];

    for (int i = t; i < n; i += 1024) deg_dinv[i] = rsqrtf(deg_dinv[i]);
}

__global__ void fill_kernel(const int* __restrict__ src,
                            const int* __restrict__ dst,
                            const float* __restrict__ ew,
                            const float* __restrict__ dinv,
                            int* __restrict__ cursor,
                            int2* __restrict__ csr, int e) {
    int i = blockIdx.x * blockDim.x + threadIdx.x;
    if (i >= e) return;
    int s = src[i];
    int d = dst[i];
    int pos = atomicAdd(cursor + s, 1);
    int2 p;
    p.x = d;
    p.y = __float_as_int(dinv[s] * ew[i] * dinv[d]);
    csr[pos] = p;
}

// ---------------------------------------------------------------------------
// Bias-broadcast init kernels (agg starts at +bias; reds add the rest)
// ---------------------------------------------------------------------------
__global__ void init_bias128(float* __restrict__ out,
                             const float* __restrict__ bias, int n) {
    int idx = blockIdx.x * blockDim.x + threadIdx.x;   // float4 index
    if (idx < n * 32) {
        float4 bv = ((const float4*)bias)[idx & 31];
        ((float4*)out)[idx] = bv;
    }
}

__global__ void init_bias40(float* __restrict__ out,
                            const float* __restrict__ bias, int n) {
    int idx = blockIdx.x * blockDim.x + threadIdx.x;   // float4 index
    if (idx < n * 10) {
        float4 bv = ((const float4*)bias)[idx % 10];
        ((float4*)out)[idx] = bv;
    }
}

// ---------------------------------------------------------------------------
// Fused layer: [n,128] @ [128,128] GEMM + self-loop + edge scatter (red.add).
// BM=128, BN=128, BK=16, 256 threads. h tile never touches gmem.
// ---------------------------------------------------------------------------
template <bool RELU_IN>
__global__ void __launch_bounds__(256, 2)
gcn_layer128(const float* __restrict__ A,
             const float* __restrict__ W,
             const int* __restrict__ offsets,
             const int2* __restrict__ csr,
             const float* __restrict__ dinv,
             float* __restrict__ agg, int n) {
    __shared__ float As[16][128];   // As[k][m]
    __shared__ float Bs[16][128];   // Bs[k][n]
    extern __shared__ float hs[];   // 128 rows, stride 132 (conflict-free)

    const int tid = threadIdx.x;
    const int tx = tid & 15;        // N dim
    const int ty = tid >> 4;        // M dim
    const int rb = blockIdx.x * 128;

    float acc[8][8];
#pragma unroll
    for (int i = 0; i < 8; i++)
#pragma unroll
        for (int j = 0; j < 8; j++) acc[i][j] = 0.0f;

    for (int k0 = 0; k0 < 128; k0 += 16) {
#pragma unroll
        for (int l = 0; l < 2; l++) {
            int f = tid + l * 256;
            int row = f >> 2;
            int c4 = (f & 3) * 4;
            float4 v = make_float4(0.f, 0.f, 0.f, 0.f);
            int gr = rb + row;
            if (gr < n) v = *(const float4*)(A + (size_t)gr * 128 + k0 + c4);
            if (RELU_IN) {
                v.x = fmaxf(v.x, 0.f); v.y = fmaxf(v.y, 0.f);
                v.z = fmaxf(v.z, 0.f); v.w = fmaxf(v.w, 0.f);
            }
            As[c4 + 0][row] = v.x;
            As[c4 + 1][row] = v.y;
            As[c4 + 2][row] = v.z;
            As[c4 + 3][row] = v.w;
        }
#pragma unroll
        for (int l = 0; l < 2; l++) {
            int f = tid + l * 256;
            int kr = f >> 5;
            int c = (f & 31) * 4;
            *(float4*)&Bs[kr][c] = *(const float4*)(W + (size_t)(k0 + kr) * 128 + c);
        }
        __syncthreads();

#pragma unroll
        for (int k = 0; k < 16; k++) {
            float4 a0 = *(const float4*)&As[k][ty * 8];
            float4 a1 = *(const float4*)&As[k][ty * 8 + 4];
            float4 b0 = *(const float4*)&Bs[k][tx * 8];
            float4 b1 = *(const float4*)&Bs[k][tx * 8 + 4];
            float a[8] = {a0.x, a0.y, a0.z, a0.w, a1.x, a1.y, a1.z, a1.w};
            float b[8] = {b0.x, b0.y, b0.z, b0.w, b1.x, b1.y, b1.z, b1.w};
#pragma unroll
            for (int i = 0; i < 8; i++)
#pragma unroll
                for (int j = 0; j < 8; j++)
                    acc[i][j] = fmaf(a[i], b[j], acc[i][j]);
        }
        __syncthreads();
    }

    // Stage h tile to smem (padded stride 132)
#pragma unroll
    for (int i = 0; i < 8; i++) {
        int row = ty * 8 + i;
#pragma unroll
        for (int j = 0; j < 8; j += 4) {
            *(float4*)&hs[row * 132 + tx * 8 + j] =
                make_float4(acc[i][j], acc[i][j + 1], acc[i][j + 2], acc[i][j + 3]);
        }
    }
    __syncthreads();

    // Scatter phase: warp w owns rows w*16 .. w*16+15
    const int lane = tid & 31;
    const int w = tid >> 5;
    for (int rr = 0; rr < 16; rr++) {
        int r = w * 16 + rr;
        int g = rb + r;
        if (g >= n) break;
        float4 rv = *(const float4*)&hs[r * 132 + lane * 4];
        float di = dinv[g];
        di *= di;
        red4(agg + (size_t)g * 128 + lane * 4,
             rv.x * di, rv.y * di, rv.z * di, rv.w * di);

        int beg = offsets[g];
        int end = offsets[g + 1];
        int j = beg;
        for (; j + 2 <= end; j += 2) {
            int2 p0 = csr[j];
            int2 p1 = csr[j + 1];
            float n0 = __int_as_float(p0.y);
            float n1 = __int_as_float(p1.y);
            red4(agg + (size_t)p0.x * 128 + lane * 4,
                 rv.x * n0, rv.y * n0, rv.z * n0, rv.w * n0);
            red4(agg + (size_t)p1.x * 128 + lane * 4,
                 rv.x * n1, rv.y * n1, rv.z * n1, rv.w * n1);
        }
        if (j < end) {
            int2 p = csr[j];
            float nm = __int_as_float(p.y);
            red4(agg + (size_t)p.x * 128 + lane * 4,
                 rv.x * nm, rv.y * nm, rv.z * nm, rv.w * nm);
        }
    }
}

// ---------------------------------------------------------------------------
// Fused layer 3: relu(A)[n,128] @ [128,40] + self-loop + edge scatter.
// 64 rows/block, 128 threads (4 warps).
// ---------------------------------------------------------------------------
__global__ void __launch_bounds__(128)
gcn_layer40(const float* __restrict__ A,
            const float* __restrict__ W,
            const int* __restrict__ offsets,
            const int2* __restrict__ csr,
            const float* __restrict__ dinv,
            float* __restrict__ out, int n) {
    extern __shared__ float sm[];
    float* xs = sm;                 // 64 rows, stride 129
    float* ws = sm + 64 * 129;      // 128*40

    const int tid = threadIdx.x;
    const int rb = blockIdx.x * 64;

    for (int l = tid * 4; l < 128 * 40; l += 128 * 4)
        *(float4*)(ws + l) = *(const float4*)(W + l);

    for (int f = tid; f < 2048; f += 128) {
        int row = f >> 5;
        int c = (f & 31) * 4;
        float4 v = make_float4(0.f, 0.f, 0.f, 0.f);
        int gr = rb + row;
        if (gr < n) v = *(const float4*)(A + (size_t)gr * 128 + c);
        float* xr = xs + row * 129 + c;
        xr[0] = fmaxf(v.x, 0.f);
        xr[1] = fmaxf(v.y, 0.f);
        xr[2] = fmaxf(v.z, 0.f);
        xr[3] = fmaxf(v.w, 0.f);
    }
    __syncthreads();

    const int tc = tid & 7;     // cols tc + 8j, j<5
    const int tr = tid >> 3;    // rows tr*4 .. tr*4+3
    float acc[4][5];
#pragma unroll
    for (int r = 0; r < 4; r++)
#pragma unroll
        for (int j = 0; j < 5; j++) acc[r][j] = 0.0f;

#pragma unroll 4
    for (int k = 0; k < 128; k++) {
        float wv[5];
#pragma unroll
        for (int j = 0; j < 5; j++) wv[j] = ws[k * 40 + tc + 8 * j];
#pragma unroll
        for (int r = 0; r < 4; r++) {
            float a = xs[(tr * 4 + r) * 129 + k];
#pragma unroll
            for (int j = 0; j < 5; j++) acc[r][j] = fmaf(a, wv[j], acc[r][j]);
        }
    }
    __syncthreads();   // all xs reads done; overlay hs on xs region

    float* hs = sm;    // 64 rows, stride 40
#pragma unroll
    for (int r = 0; r < 4; r++)
#pragma unroll
        for (int j = 0; j < 5; j++)
            hs[(tr * 4 + r) * 40 + tc + 8 * j] = acc[r][j];
    __syncthreads();

    // Scatter: warp w owns rows w*16 .. w*16+15; lanes 0..9 carry the row
    const int lane = tid & 31;
    const int w = tid >> 5;
    for (int rr = 0; rr < 16; rr++) {
        int r = w * 16 + rr;
        int g = rb + r;
        if (g >= n) break;
        float4 rv = make_float4(0.f, 0.f, 0.f, 0.f);
        if (lane < 10) rv = *(const float4*)&hs[r * 40 + lane * 4];
        float di = dinv[g];
        di *= di;
        if (lane < 10)
            red4(out + (size_t)g * 40 + lane * 4,
                 rv.x * di, rv.y * di, rv.z * di, rv.w * di);

        int beg = offsets[g];
        int end = offsets[g + 1];
        for (int j = beg; j < end; j++) {
            int2 p = csr[j];
            float nm = __int_as_float(p.y);
            if (lane < 10)
                red4(out + (size_t)p.x * 40 + lane * 4,
                     rv.x * nm, rv.y * nm, rv.z * nm, rv.w * nm);
        }
    }
}

// ---------------------------------------------------------------------------
// Launch
// ---------------------------------------------------------------------------
extern "C" void kernel_launch(void* const* d_in, const int* in_sizes, int n_in,
                              void* d_out, int out_size) {
    const float* x  = (const float*)d_in[0];
    const int*   ei = (const int*)d_in[1];
    const float* ew = (const float*)d_in[2];
    const float* W1 = (const float*)d_in[3];
    const float* b1 = (const float*)d_in[4];
    const float* W2 = (const float*)d_in[5];
    const float* b2 = (const float*)d_in[6];
    const float* W3 = (const float*)d_in[7];
    const float* b3 = (const float*)d_in[8];
    float* out = (float*)d_out;

    const int n = in_sizes[0] / 128;       // 50000
    const int e = in_sizes[2];             // 640000
    const int* src = ei;
    const int* dst = ei + e;

    int *count, *offsets, *cursor;
    int2* csr;
    float *dinv, *agg1, *agg2;
    cudaGetSymbolAddress((void**)&count,   g_count);
    cudaGetSymbolAddress((void**)&dinv,    g_dinv);
    cudaGetSymbolAddress((void**)&offsets, g_offsets);
    cudaGetSymbolAddress((void**)&cursor,  g_cursor);
    cudaGetSymbolAddress((void**)&csr,     g_csr);
    cudaGetSymbolAddress((void**)&agg1,    g_agg1);
    cudaGetSymbolAddress((void**)&agg2,    g_agg2);

    const int nb_n = (n + 255) / 256;
    const int nb_e = (e + 255) / 256;

    // CSR build (by src) + dinv
    zero_kernel<<<nb_n, 256>>>(count, dinv, n);
    hist_kernel<<<nb_e, 256>>>(src, dst, ew, count, dinv, e);
    scan_kernel<<<1, 1024>>>(count, dinv, offsets, cursor, n);
    fill_kernel<<<nb_e, 256>>>(src, dst, ew, dinv, cursor, csr, e);

    const int l128_blocks = (n + 127) / 128;
    const int l128_smem = 128 * 132 * sizeof(float);   // 67584 B
    cudaFuncSetAttribute(gcn_layer128<false>,
                         cudaFuncAttributeMaxDynamicSharedMemorySize, l128_smem);
    cudaFuncSetAttribute(gcn_layer128<true>,
                         cudaFuncAttributeMaxDynamicSharedMemorySize, l128_smem);

    const int l40_blocks = (n + 63) / 64;
    const int l40_smem = (64 * 129 + 128 * 40) * sizeof(float);   // 53504 B
    cudaFuncSetAttribute(gcn_layer40,
                         cudaFuncAttributeMaxDynamicSharedMemorySize, l40_smem);

    // Layer 1
    init_bias128<<<(n * 32 + 255) / 256, 256>>>(agg1, b1, n);
    gcn_layer128<false><<<l128_blocks, 256, l128_smem>>>(x, W1, offsets, csr, dinv, agg1, n);

    // Layer 2 (relu fused into A-load)
    init_bias128<<<(n * 32 + 255) / 256, 256>>>(agg2, b2, n);
    gcn_layer128<true><<<l128_blocks, 256, l128_smem>>>(agg1, W2, offsets, csr, dinv, agg2, n);

    // Layer 3 (relu fused; scatter straight to d_out)
    init_bias40<<<(n * 10 + 255) / 256, 256>>>(out, b3, n);
    gcn_layer40<<<l40_blocks, 128, l40_smem>>>(agg2, W3, offsets, csr, dinv, out, n);
}

// round 4
// speedup vs baseline: 1.2838x; 1.1331x over previous
#include <cuda_runtime.h>

// Problem constants (fixed by the dataset)
#define NMAX 50000
#define EMAX 640000

// Scratch (__device__ globals; no allocation allowed)
__device__ int   g_count[NMAX];           // out-degree counts (by src)
__device__ float g_dinv[NMAX];            // weighted in-degree (incl self) -> rsqrt
__device__ int   g_offsets[NMAX + 1];     // CSR row offsets (by src)
__device__ int   g_cursor[NMAX];          // fill cursors
__device__ int2  g_csr[EMAX];             // payload: {dst, __float_as_int(norm)}
__device__ float g_h[NMAX * 128];         // GEMM output (pre-aggregation)
__device__ float g_agg1[NMAX * 128];      // layer-1 aggregation output
__device__ float g_agg2[NMAX * 128];      // layer-2 aggregation output
__device__ float g_h3[NMAX * 40];         // layer-3 GEMM output

__device__ __forceinline__ void red4(float* p, float a, float b, float c, float d) {
    asm volatile("red.global.add.v4.f32 [%0], {%1, %2, %3, %4};"
                 :: "l"(p), "f"(a), "f"(b), "f"(c), "f"(d) : "memory");
}

// ---------------------------------------------------------------------------
// CSR build (by src) + degree normalization (by dst)
// ---------------------------------------------------------------------------
__global__ void zero_kernel(int* count, float* deg, int n) {
    int i = blockIdx.x * blockDim.x + threadIdx.x;
    if (i < n) { count[i] = 0; deg[i] = 1.0f; }  // self-loop weight
}

__global__ void hist_kernel(const int* __restrict__ src,
                            const int* __restrict__ dst,
                            const float* __restrict__ ew,
                            int* __restrict__ count,
                            float* __restrict__ deg, int e) {
    int i = blockIdx.x * blockDim.x + threadIdx.x;
    if (i < e) {
        atomicAdd(count + src[i], 1);
        atomicAdd(deg + dst[i], ew[i]);
    }
}

// Single-block exclusive scan of count[n] -> offsets/cursor; deg -> rsqrt(deg).
__global__ void __launch_bounds__(1024)
scan_kernel(const int* __restrict__ count,
            float* __restrict__ deg_dinv,
            int* __restrict__ offsets,
            int* __restrict__ cursor, int n) {
    __shared__ int part[1024];
    const int t = threadIdx.x;
    const int C = (n + 1023) / 1024;
    const int base = t * C;

    int sum = 0;
    for (int i = 0; i < C; i++) {
        int idx = base + i;
        sum += (idx < n) ? count[idx] : 0;
    }
    part[t] = sum;
    __syncthreads();
    for (int off = 1; off < 1024; off <<= 1) {
        int v = (t >= off) ? part[t - off] : 0;
        __syncthreads();
        part[t] += v;
        __syncthreads();
    }
    int run = (t > 0) ? part[t - 1] : 0;
    for (int i = 0; i < C; i++) {
        int idx = base + i;
        if (idx < n) {
            offsets[idx] = run;
            cursor[idx] = run;
            run += count[idx];
        }
    }
    if (t == 1023) offsets[n] = part[1023];

    for (int i = t; i < n; i += 1024) deg_dinv[i] = rsqrtf(deg_dinv[i]);
}

__global__ void fill_kernel(const int* __restrict__ src,
                            const int* __restrict__ dst,
                            const float* __restrict__ ew,
                            const float* __restrict__ dinv,
                            int* __restrict__ cursor,
                            int2* __restrict__ csr, int e) {
    int i = blockIdx.x * blockDim.x + threadIdx.x;
    if (i >= e) return;
    int s = src[i];
    int d = dst[i];
    int pos = atomicAdd(cursor + s, 1);
    int2 p;
    p.x = d;
    p.y = __float_as_int(dinv[s] * ew[i] * dinv[d]);
    csr[pos] = p;
}

// ---------------------------------------------------------------------------
// Bias-broadcast init kernels (agg starts at +bias; reds add the rest)
// ---------------------------------------------------------------------------
__global__ void init_bias128(float* __restrict__ out,
                             const float* __restrict__ bias, int n) {
    int idx = blockIdx.x * blockDim.x + threadIdx.x;   // float4 index
    if (idx < n * 32) {
        float4 bv = ((const float4*)bias)[idx & 31];
        ((float4*)out)[idx] = bv;
    }
}

__global__ void init_bias40(float* __restrict__ out,
                            const float* __restrict__ bias, int n) {
    int idx = blockIdx.x * blockDim.x + threadIdx.x;   // float4 index
    if (idx < n * 10) {
        float4 bv = ((const float4*)bias)[idx % 10];
        ((float4*)out)[idx] = bv;
    }
}

// ---------------------------------------------------------------------------
// GEMM: [n,128] @ [128,128] -> H only. Optional ReLU on the A operand.
// BM=128, BN=128, BK=16, 256 threads, 8x8 microtile. (round-1 kernel)
// ---------------------------------------------------------------------------
template <bool RELU_IN>
__global__ void __launch_bounds__(256, 2)
gemm128_kernel(const float* __restrict__ A,
               const float* __restrict__ W,
               float* __restrict__ Hout,
               int n) {
    __shared__ float As[16][128];
    __shared__ float Bs[16][128];

    const int tid = threadIdx.x;
    const int tx = tid & 15;
    const int ty = tid >> 4;
    const int rb = blockIdx.x * 128;

    float acc[8][8];
#pragma unroll
    for (int i = 0; i < 8; i++)
#pragma unroll
        for (int j = 0; j < 8; j++) acc[i][j] = 0.0f;

    for (int k0 = 0; k0 < 128; k0 += 16) {
#pragma unroll
        for (int l = 0; l < 2; l++) {
            int f = tid + l * 256;
            int row = f >> 2;
            int c4 = (f & 3) * 4;
            float4 v = make_float4(0.f, 0.f, 0.f, 0.f);
            int gr = rb + row;
            if (gr < n) v = *(const float4*)(A + (size_t)gr * 128 + k0 + c4);
            if (RELU_IN) {
                v.x = fmaxf(v.x, 0.f); v.y = fmaxf(v.y, 0.f);
                v.z = fmaxf(v.z, 0.f); v.w = fmaxf(v.w, 0.f);
            }
            As[c4 + 0][row] = v.x;
            As[c4 + 1][row] = v.y;
            As[c4 + 2][row] = v.z;
            As[c4 + 3][row] = v.w;
        }
#pragma unroll
        for (int l = 0; l < 2; l++) {
            int f = tid + l * 256;
            int kr = f >> 5;
            int c = (f & 31) * 4;
            *(float4*)&Bs[kr][c] = *(const float4*)(W + (size_t)(k0 + kr) * 128 + c);
        }
        __syncthreads();

#pragma unroll
        for (int k = 0; k < 16; k++) {
            float4 a0 = *(const float4*)&As[k][ty * 8];
            float4 a1 = *(const float4*)&As[k][ty * 8 + 4];
            float4 b0 = *(const float4*)&Bs[k][tx * 8];
            float4 b1 = *(const float4*)&Bs[k][tx * 8 + 4];
            float a[8] = {a0.x, a0.y, a0.z, a0.w, a1.x, a1.y, a1.z, a1.w};
            float b[8] = {b0.x, b0.y, b0.z, b0.w, b1.x, b1.y, b1.z, b1.w};
#pragma unroll
            for (int i = 0; i < 8; i++)
#pragma unroll
                for (int j = 0; j < 8; j++)
                    acc[i][j] = fmaf(a[i], b[j], acc[i][j]);
        }
        __syncthreads();
    }

#pragma unroll
    for (int i = 0; i < 8; i++) {
        int row = rb + ty * 8 + i;
        if (row >= n) break;
#pragma unroll
        for (int j = 0; j < 8; j += 4) {
            int col = tx * 8 + j;
            *(float4*)(Hout + (size_t)row * 128 + col) =
                make_float4(acc[i][j], acc[i][j + 1], acc[i][j + 2], acc[i][j + 3]);
        }
    }
}

// ---------------------------------------------------------------------------
// CSR-by-src scatter (128 feats): one warp per src node; row loaded once.
// ---------------------------------------------------------------------------
__global__ void __launch_bounds__(256)
scatter128_csr(const float* __restrict__ h,
               const int2* __restrict__ csr,
               const int* __restrict__ offsets,
               const float* __restrict__ dinv,
               float* __restrict__ agg, int n) {
    int v = (blockIdx.x * blockDim.x + threadIdx.x) >> 5;
    int lane = threadIdx.x & 31;
    if (v >= n) return;

    float4 rv = *(const float4*)(h + (size_t)v * 128 + lane * 4);
    float di = dinv[v];
    di *= di;
    red4(agg + (size_t)v * 128 + lane * 4,
         rv.x * di, rv.y * di, rv.z * di, rv.w * di);

    int beg = offsets[v];
    int end = offsets[v + 1];
    int j = beg;
    for (; j + 2 <= end; j += 2) {
        int2 p0 = csr[j];
        int2 p1 = csr[j + 1];
        float n0 = __int_as_float(p0.y);
        float n1 = __int_as_float(p1.y);
        red4(agg + (size_t)p0.x * 128 + lane * 4,
             rv.x * n0, rv.y * n0, rv.z * n0, rv.w * n0);
        red4(agg + (size_t)p1.x * 128 + lane * 4,
             rv.x * n1, rv.y * n1, rv.z * n1, rv.w * n1);
    }
    if (j < end) {
        int2 p = csr[j];
        float nm = __int_as_float(p.y);
        red4(agg + (size_t)p.x * 128 + lane * 4,
             rv.x * nm, rv.y * nm, rv.z * nm, rv.w * nm);
    }
}

// ---------------------------------------------------------------------------
// Layer-3 GEMM: relu(A)[n,128] @ [128,40] -> H3. (round-1 kernel)
// ---------------------------------------------------------------------------
__global__ void __launch_bounds__(128)
gemm40_kernel(const float* __restrict__ A,
              const float* __restrict__ W,
              float* __restrict__ Hout, int n) {
    extern __shared__ float sm[];
    float* xs = sm;                 // 64 rows, stride 129
    float* ws = sm + 64 * 129;      // 128*40

    const int tid = threadIdx.x;
    const int rb = blockIdx.x * 64;

    for (int l = tid * 4; l < 128 * 40; l += 128 * 4)
        *(float4*)(ws + l) = *(const float4*)(W + l);

    for (int f = tid; f < 2048; f += 128) {
        int row = f >> 5;
        int c = (f & 31) * 4;
        float4 v = make_float4(0.f, 0.f, 0.f, 0.f);
        int gr = rb + row;
        if (gr < n) v = *(const float4*)(A + (size_t)gr * 128 + c);
        float* xr = xs + row * 129 + c;
        xr[0] = fmaxf(v.x, 0.f);
        xr[1] = fmaxf(v.y, 0.f);
        xr[2] = fmaxf(v.z, 0.f);
        xr[3] = fmaxf(v.w, 0.f);
    }
    __syncthreads();

    const int tc = tid & 7;
    const int tr = tid >> 3;
    float acc[4][5];
#pragma unroll
    for (int r = 0; r < 4; r++)
#pragma unroll
        for (int j = 0; j < 5; j++) acc[r][j] = 0.0f;

#pragma unroll 4
    for (int k = 0; k < 128; k++) {
        float wv[5];
#pragma unroll
        for (int j = 0; j < 5; j++) wv[j] = ws[k * 40 + tc + 8 * j];
#pragma unroll
        for (int r = 0; r < 4; r++) {
            float a = xs[(tr * 4 + r) * 129 + k];
#pragma unroll
            for (int j = 0; j < 5; j++) acc[r][j] = fmaf(a, wv[j], acc[r][j]);
        }
    }

#pragma unroll
    for (int r = 0; r < 4; r++) {
        int row = rb + tr * 4 + r;
        if (row >= n) break;
#pragma unroll
        for (int j = 0; j < 5; j++)
            Hout[(size_t)row * 40 + tc + 8 * j] = acc[r][j];
    }
}

// ---------------------------------------------------------------------------
// CSR-by-src scatter (40 feats): one warp per src node, lanes 0..9 active.
// ---------------------------------------------------------------------------
__global__ void __launch_bounds__(256)
scatter40_csr(const float* __restrict__ h,
              const int2* __restrict__ csr,
              const int* __restrict__ offsets,
              const float* __restrict__ dinv,
              float* __restrict__ out, int n) {
    int v = (blockIdx.x * blockDim.x + threadIdx.x) >> 5;
    int lane = threadIdx.x & 31;
    if (v >= n) return;

    int beg = offsets[v];
    int end = offsets[v + 1];

    float4 rv = make_float4(0.f, 0.f, 0.f, 0.f);
    if (lane < 10) {
        rv = *(const float4*)(h + (size_t)v * 40 + lane * 4);
        float di = dinv[v];
        di *= di;
        red4(out + (size_t)v * 40 + lane * 4,
             rv.x * di, rv.y * di, rv.z * di, rv.w * di);
    }
    for (int j = beg; j < end; j++) {
        int2 p = csr[j];
        float nm = __int_as_float(p.y);
        if (lane < 10)
            red4(out + (size_t)p.x * 40 + lane * 4,
                 rv.x * nm, rv.y * nm, rv.z * nm, rv.w * nm);
    }
}

// ---------------------------------------------------------------------------
// Launch
// ---------------------------------------------------------------------------
extern "C" void kernel_launch(void* const* d_in, const int* in_sizes, int n_in,
                              void* d_out, int out_size) {
    const float* x  = (const float*)d_in[0];
    const int*   ei = (const int*)d_in[1];
    const float* ew = (const float*)d_in[2];
    const float* W1 = (const float*)d_in[3];
    const float* b1 = (const float*)d_in[4];
    const float* W2 = (const float*)d_in[5];
    const float* b2 = (const float*)d_in[6];
    const float* W3 = (const float*)d_in[7];
    const float* b3 = (const float*)d_in[8];
    float* out = (float*)d_out;

    const int n = in_sizes[0] / 128;       // 50000
    const int e = in_sizes[2];             // 640000
    const int* src = ei;
    const int* dst = ei + e;

    int *count, *offsets, *cursor;
    int2* csr;
    float *dinv, *h, *agg1, *agg2, *h3;
    cudaGetSymbolAddress((void**)&count,   g_count);
    cudaGetSymbolAddress((void**)&dinv,    g_dinv);
    cudaGetSymbolAddress((void**)&offsets, g_offsets);
    cudaGetSymbolAddress((void**)&cursor,  g_cursor);
    cudaGetSymbolAddress((void**)&csr,     g_csr);
    cudaGetSymbolAddress((void**)&h,       g_h);
    cudaGetSymbolAddress((void**)&agg1,    g_agg1);
    cudaGetSymbolAddress((void**)&agg2,    g_agg2);
    cudaGetSymbolAddress((void**)&h3,      g_h3);

    const int nb_n = (n + 255) / 256;
    const int nb_e = (e + 255) / 256;

    // CSR build (by src) + dinv
    zero_kernel<<<nb_n, 256>>>(count, dinv, n);
    hist_kernel<<<nb_e, 256>>>(src, dst, ew, count, dinv, e);
    scan_kernel<<<1, 1024>>>(count, dinv, offsets, cursor, n);
    fill_kernel<<<nb_e, 256>>>(src, dst, ew, dinv, cursor, csr, e);

    const int gemm_blocks = (n + 127) / 128;
    const int warp_blocks = (n * 32 + 255) / 256;   // one warp per node

    // Layer 1
    init_bias128<<<(n * 32 + 255) / 256, 256>>>(agg1, b1, n);
    gemm128_kernel<false><<<gemm_blocks, 256>>>(x, W1, h, n);
    scatter128_csr<<<warp_blocks, 256>>>(h, csr, offsets, dinv, agg1, n);

    // Layer 2 (relu fused into GEMM A-load)
    init_bias128<<<(n * 32 + 255) / 256, 256>>>(agg2, b2, n);
    gemm128_kernel<true><<<gemm_blocks, 256>>>(agg1, W2, h, n);
    scatter128_csr<<<warp_blocks, 256>>>(h, csr, offsets, dinv, agg2, n);

    // Layer 3 (relu fused; scatter straight to d_out)
    static const int g40_smem = (64 * 129 + 128 * 40) * sizeof(float);
    cudaFuncSetAttribute(gemm40_kernel,
                         cudaFuncAttributeMaxDynamicSharedMemorySize, g40_smem);
    init_bias40<<<(n * 10 + 255) / 256, 256>>>(out, b3, n);
    gemm40_kernel<<<(n + 63) / 64, 128, g40_smem>>>(agg2, W3, h3, n);
    scatter40_csr<<<warp_blocks, 256>>>(h3, csr, offsets, dinv, out, n);
}

// round 5
// speedup vs baseline: 1.5364x; 1.1968x over previous
#include <cuda_runtime.h>
#include <cstdint>

// Problem constants (fixed by the dataset)
#define NMAX 50000
#define EMAX 640000

// Scratch (allocation-free rule: __device__ globals)
__device__ float g_dinv[NMAX];          // deg -> rsqrt(deg) in place
__device__ float g_norm[EMAX];          // per-edge normalization
__device__ float g_h[NMAX * 128];       // GEMM output (pre-aggregation)
__device__ float g_agg[NMAX * 128];     // aggregation buffer (init + scatter)
__device__ float g_h3[NMAX * 40];       // layer-3 GEMM output
// W fragments (mma layout), hi/lo tf32 split: [16 chunks][16 ntiles][32 lanes] float2
__device__ float g_wf1_hi[16384];
__device__ float g_wf1_lo[16384];
__device__ float g_wf2_hi[16384];
__device__ float g_wf2_lo[16384];

// ---------------------------------------------------------------------------
// tf32 helpers
// ---------------------------------------------------------------------------
__device__ __forceinline__ uint32_t f2tf32(float x) {
    uint32_t r;
    asm("cvt.rna.tf32.f32 %0, %1;" : "=r"(r) : "f"(x));
    return r;
}

__device__ __forceinline__ void mma_tf32(float* c, const uint32_t* a, const uint32_t* b) {
    asm volatile(
        "mma.sync.aligned.m16n8k8.row.col.f32.tf32.tf32.f32 "
        "{%0,%1,%2,%3}, {%4,%5,%6,%7}, {%8,%9}, {%0,%1,%2,%3};"
        : "+f"(c[0]), "+f"(c[1]), "+f"(c[2]), "+f"(c[3])
        : "r"(a[0]), "r"(a[1]), "r"(a[2]), "r"(a[3]), "r"(b[0]), "r"(b[1]));
}

// ---------------------------------------------------------------------------
// Degree / normalization precompute (round-1, proven)
// ---------------------------------------------------------------------------
__global__ void deg_init_kernel(float* deg, int n) {
    int i = blockIdx.x * blockDim.x + threadIdx.x;
    if (i < n) deg[i] = 1.0f;  // self-loop weight
}

__global__ void deg_acc_kernel(const int* __restrict__ dst,
                               const float* __restrict__ ew,
                               float* deg, int e) {
    int i = blockIdx.x * blockDim.x + threadIdx.x;
    if (i < e) atomicAdd(deg + dst[i], ew[i]);
}

__global__ void dinv_kernel(float* deg, int n) {
    int i = blockIdx.x * blockDim.x + threadIdx.x;
    if (i < n) deg[i] = rsqrtf(deg[i]);  // deg >= 1 always
}

__global__ void norm_kernel(const int* __restrict__ src,
                            const int* __restrict__ dst,
                            const float* __restrict__ ew,
                            const float* __restrict__ dinv,
                            float* __restrict__ nrm, int e) {
    int i = blockIdx.x * blockDim.x + threadIdx.x;
    if (i < e) nrm[i] = dinv[src[i]] * ew[i] * dinv[dst[i]];
}

// ---------------------------------------------------------------------------
// W -> mma-fragment layout (hi/lo tf32). 16 chunks x 16 ntiles x 32 lanes.
// Fragment lane mapping (m16n8k8.row.col B): b0=(k=lane&3, n=lane>>2), b1=k+4.
// ---------------------------------------------------------------------------
__global__ void wfrag_kernel(const float* __restrict__ W,
                             float* __restrict__ hi, float* __restrict__ lo) {
    int t = blockIdx.x * blockDim.x + threadIdx.x;
    if (t >= 16 * 16 * 32) return;
    int lane = t & 31;
    int ntile = (t >> 5) & 15;
    int chunk = t >> 9;
    int k = chunk * 8 + (lane & 3);
    int nn = ntile * 8 + (lane >> 2);
    float w0 = W[k * 128 + nn];
    float w1 = W[(k + 4) * 128 + nn];
    uint32_t h0 = f2tf32(w0), h1 = f2tf32(w1);
    float hf0 = __uint_as_float(h0), hf1 = __uint_as_float(h1);
    float2 H = make_float2(hf0, hf1);
    float2 L = make_float2(__uint_as_float(f2tf32(w0 - hf0)),
                           __uint_as_float(f2tf32(w1 - hf1)));
    *(float2*)(hi + (size_t)t * 2) = H;
    *(float2*)(lo + (size_t)t * 2) = L;
}

// ---------------------------------------------------------------------------
// Tensor-core GEMM (3xTF32): [n,128] @ [128,128] -> H and AGG init.
// 256 threads = 8 warps (2x4 warp grid), warp tile 64x32, mma m16n8k8.
// A staged via smem in (k,k+4)-pair float2 layout; B fragments from gmem.
// ---------------------------------------------------------------------------
template <bool RELU_IN>
__global__ void __launch_bounds__(256)
gemm128_tc(const float* __restrict__ A,
           const float* __restrict__ wf_hi,
           const float* __restrict__ wf_lo,
           const float* __restrict__ bias,
           const float* __restrict__ dinv,
           float* __restrict__ Hout,
           float* __restrict__ AggOut,
           int n) {
    // pair layout float index: m*16 + chunk*8 + pair*2 + half
    __shared__ float As_hi[128 * 16];
    __shared__ float As_lo[128 * 16];

    const int tid = threadIdx.x;
    const int lane = tid & 31;
    const int wid = tid >> 5;
    const int wm = wid >> 2;   // 0..1  (64-row slabs)
    const int wn = wid & 3;    // 0..3  (32-col slabs)
    const int rb = blockIdx.x * 128;

    const int ld_row = tid >> 2;           // 0..63 (+64 for second batch)
    const int ld_c4 = (tid & 3) * 4;       // 0,4,8,12
    const int ld_chunk = ld_c4 >> 3;       // 0/1
    const int ld_half = (ld_c4 >> 2) & 1;  // 0/1

    float c[4][4][4];
#pragma unroll
    for (int mi = 0; mi < 4; mi++)
#pragma unroll
        for (int ni = 0; ni < 4; ni++)
#pragma unroll
            for (int r = 0; r < 4; r++) c[mi][ni][r] = 0.0f;

    // prefetch stage 0
    float4 pv[2];
#pragma unroll
    for (int l = 0; l < 2; l++) {
        int row = ld_row + l * 64;
        int gr = rb + row;
        float4 v = make_float4(0.f, 0.f, 0.f, 0.f);
        if (gr < n) v = *(const float4*)(A + (size_t)gr * 128 + ld_c4);
        if (RELU_IN) {
            v.x = fmaxf(v.x, 0.f); v.y = fmaxf(v.y, 0.f);
            v.z = fmaxf(v.z, 0.f); v.w = fmaxf(v.w, 0.f);
        }
        pv[l] = v;
    }

    for (int s = 0; s < 8; s++) {
        __syncthreads();
        // store prefetched A with tf32 hi/lo split
#pragma unroll
        for (int l = 0; l < 2; l++) {
            int row = ld_row + l * 64;
            float* bh = As_hi + row * 16 + ld_chunk * 8 + ld_half;
            float* bl = As_lo + row * 16 + ld_chunk * 8 + ld_half;
            float vv[4] = {pv[l].x, pv[l].y, pv[l].z, pv[l].w};
#pragma unroll
            for (int p = 0; p < 4; p++) {
                uint32_t hb = f2tf32(vv[p]);
                float hf = __uint_as_float(hb);
                bh[p * 2] = hf;
                bl[p * 2] = __uint_as_float(f2tf32(vv[p] - hf));
            }
        }
        __syncthreads();

        // prefetch next stage
        if (s < 7) {
            int k0 = (s + 1) * 16;
#pragma unroll
            for (int l = 0; l < 2; l++) {
                int row = ld_row + l * 64;
                int gr = rb + row;
                float4 v = make_float4(0.f, 0.f, 0.f, 0.f);
                if (gr < n) v = *(const float4*)(A + (size_t)gr * 128 + k0 + ld_c4);
                if (RELU_IN) {
                    v.x = fmaxf(v.x, 0.f); v.y = fmaxf(v.y, 0.f);
                    v.z = fmaxf(v.z, 0.f); v.w = fmaxf(v.w, 0.f);
                }
                pv[l] = v;
            }
        }

        // compute: 2 k-chunks of 8
#pragma unroll
        for (int kc = 0; kc < 2; kc++) {
            int gchunk = s * 2 + kc;
            uint32_t bh[4][2], bl[4][2];
#pragma unroll
            for (int ni = 0; ni < 4; ni++) {
                size_t idx = ((size_t)(gchunk * 16 + wn * 4 + ni) * 32 + lane) * 2;
                float2 h2 = *(const float2*)(wf_hi + idx);
                float2 l2 = *(const float2*)(wf_lo + idx);
                bh[ni][0] = __float_as_uint(h2.x);
                bh[ni][1] = __float_as_uint(h2.y);
                bl[ni][0] = __float_as_uint(l2.x);
                bl[ni][1] = __float_as_uint(l2.y);
            }
#pragma unroll
            for (int mi = 0; mi < 4; mi++) {
                int m0 = wm * 64 + mi * 16 + (lane >> 2);
                const float2 ah0 = *(const float2*)(As_hi + m0 * 16 + kc * 8 + (lane & 3) * 2);
                const float2 ah1 = *(const float2*)(As_hi + (m0 + 8) * 16 + kc * 8 + (lane & 3) * 2);
                const float2 al0 = *(const float2*)(As_lo + m0 * 16 + kc * 8 + (lane & 3) * 2);
                const float2 al1 = *(const float2*)(As_lo + (m0 + 8) * 16 + kc * 8 + (lane & 3) * 2);
                uint32_t ahi[4] = {__float_as_uint(ah0.x), __float_as_uint(ah1.x),
                                   __float_as_uint(ah0.y), __float_as_uint(ah1.y)};
                uint32_t alo[4] = {__float_as_uint(al0.x), __float_as_uint(al1.x),
                                   __float_as_uint(al0.y), __float_as_uint(al1.y)};
#pragma unroll
                for (int ni = 0; ni < 4; ni++) {
                    mma_tf32(c[mi][ni], ahi, bh[ni]);   // hi*hi
                    mma_tf32(c[mi][ni], ahi, bl[ni]);   // hi*lo
                    mma_tf32(c[mi][ni], alo, bh[ni]);   // lo*hi
                }
            }
        }
    }

    // Epilogue: write H and AGG init = H*dinv^2 + bias
#pragma unroll
    for (int mi = 0; mi < 4; mi++) {
        int r0 = rb + wm * 64 + mi * 16 + (lane >> 2);
        int r1 = r0 + 8;
        bool ok0 = (r0 < n), ok1 = (r1 < n);
        float sl0 = ok0 ? dinv[r0] : 0.f;
        float sl1 = ok1 ? dinv[r1] : 0.f;
        sl0 *= sl0; sl1 *= sl1;
#pragma unroll
        for (int ni = 0; ni < 4; ni++) {
            int col = wn * 32 + ni * 8 + (lane & 3) * 2;
            float2 b2 = *(const float2*)(bias + col);
            if (ok0) {
                *(float2*)(Hout + (size_t)r0 * 128 + col) =
                    make_float2(c[mi][ni][0], c[mi][ni][1]);
                *(float2*)(AggOut + (size_t)r0 * 128 + col) =
                    make_float2(fmaf(c[mi][ni][0], sl0, b2.x),
                                fmaf(c[mi][ni][1], sl0, b2.y));
            }
            if (ok1) {
                *(float2*)(Hout + (size_t)r1 * 128 + col) =
                    make_float2(c[mi][ni][2], c[mi][ni][3]);
                *(float2*)(AggOut + (size_t)r1 * 128 + col) =
                    make_float2(fmaf(c[mi][ni][2], sl1, b2.x),
                                fmaf(c[mi][ni][3], sl1, b2.y));
            }
        }
    }
}

// ---------------------------------------------------------------------------
// Edge scatter (128 features): one warp per edge (round-1, proven)
// ---------------------------------------------------------------------------
__global__ void __launch_bounds__(256)
scatter128_kernel(const float* __restrict__ h,
                  const int* __restrict__ src,
                  const int* __restrict__ dst,
                  const float* __restrict__ nrm,
                  float* __restrict__ agg,
                  int e) {
    int warp = (blockIdx.x * blockDim.x + threadIdx.x) >> 5;
    int lane = threadIdx.x & 31;
    if (warp >= e) return;
    int s = src[warp];
    int d = dst[warp];
    float nm = nrm[warp];
    float4 v = *(const float4*)(h + (size_t)s * 128 + lane * 4);
    float rx = v.x * nm, ry = v.y * nm, rz = v.z * nm, rw = v.w * nm;
    float* p = agg + (size_t)d * 128 + lane * 4;
    asm volatile("red.global.add.v4.f32 [%0], {%1, %2, %3, %4};"
                 :: "l"(p), "f"(rx), "f"(ry), "f"(rz), "f"(rw)
                 : "memory");
}

// ---------------------------------------------------------------------------
// Layer-3 GEMM: relu(A)[n,128] @ [128,40] -> H3 and Out init (round-1, proven)
// ---------------------------------------------------------------------------
__global__ void __launch_bounds__(128)
gemm40_kernel(const float* __restrict__ A,
              const float* __restrict__ W,
              const float* __restrict__ bias,
              const float* __restrict__ dinv,
              float* __restrict__ Hout,
              float* __restrict__ Out,
              int n) {
    extern __shared__ float sm[];
    float* xs = sm;                 // 64 rows, stride 129
    float* ws = sm + 64 * 129;      // 128*40 flat

    const int tid = threadIdx.x;
    const int rb = blockIdx.x * 64;

    for (int l = tid * 4; l < 128 * 40; l += 128 * 4)
        *(float4*)(ws + l) = *(const float4*)(W + l);

    for (int f = tid; f < 2048; f += 128) {
        int row = f >> 5;
        int c = (f & 31) * 4;
        float4 v = make_float4(0.f, 0.f, 0.f, 0.f);
        int gr = rb + row;
        if (gr < n) v = *(const float4*)(A + (size_t)gr * 128 + c);
        float* xr = xs + row * 129 + c;
        xr[0] = fmaxf(v.x, 0.f);
        xr[1] = fmaxf(v.y, 0.f);
        xr[2] = fmaxf(v.z, 0.f);
        xr[3] = fmaxf(v.w, 0.f);
    }
    __syncthreads();

    const int tc = tid & 7;
    const int tr = tid >> 3;
    float acc[4][5];
#pragma unroll
    for (int r = 0; r < 4; r++)
#pragma unroll
        for (int j = 0; j < 5; j++) acc[r][j] = 0.0f;

#pragma unroll 4
    for (int k = 0; k < 128; k++) {
        float w[5];
#pragma unroll
        for (int j = 0; j < 5; j++) w[j] = ws[k * 40 + tc + 8 * j];
#pragma unroll
        for (int r = 0; r < 4; r++) {
            float a = xs[(tr * 4 + r) * 129 + k];
#pragma unroll
            for (int j = 0; j < 5; j++) acc[r][j] = fmaf(a, w[j], acc[r][j]);
        }
    }

#pragma unroll
    for (int r = 0; r < 4; r++) {
        int row = rb + tr * 4 + r;
        if (row >= n) break;
        float sl = dinv[row];
        sl = sl * sl;
#pragma unroll
        for (int j = 0; j < 5; j++) {
            int ccol = tc + 8 * j;
            float v = acc[r][j];
            Hout[(size_t)row * 40 + ccol] = v;
            Out[(size_t)row * 40 + ccol] = fmaf(v, sl, bias[ccol]);
        }
    }
}

// ---------------------------------------------------------------------------
// Edge scatter (40 features): 10 float4 chunks per edge (round-1, proven)
// ---------------------------------------------------------------------------
__global__ void __launch_bounds__(256)
scatter40_kernel(const float* __restrict__ h,
                 const int* __restrict__ src,
                 const int* __restrict__ dst,
                 const float* __restrict__ nrm,
                 float* __restrict__ out,
                 int e) {
    long long idx = (long long)blockIdx.x * blockDim.x + threadIdx.x;
    long long total = (long long)e * 10;
    if (idx >= total) return;
    int ed = (int)(idx / 10);
    int c = (int)(idx - (long long)ed * 10);
    int s = src[ed];
    int d = dst[ed];
    float nm = nrm[ed];
    float4 v = *(const float4*)(h + (size_t)s * 40 + c * 4);
    float rx = v.x * nm, ry = v.y * nm, rz = v.z * nm, rw = v.w * nm;
    float* p = out + (size_t)d * 40 + c * 4;
    asm volatile("red.global.add.v4.f32 [%0], {%1, %2, %3, %4};"
                 :: "l"(p), "f"(rx), "f"(ry), "f"(rz), "f"(rw)
                 : "memory");
}

// ---------------------------------------------------------------------------
// Launch
// ---------------------------------------------------------------------------
extern "C" void kernel_launch(void* const* d_in, const int* in_sizes, int n_in,
                              void* d_out, int out_size) {
    const float* x  = (const float*)d_in[0];
    const int*   ei = (const int*)d_in[1];
    const float* ew = (const float*)d_in[2];
    const float* W1 = (const float*)d_in[3];
    const float* b1 = (const float*)d_in[4];
    const float* W2 = (const float*)d_in[5];
    const float* b2 = (const float*)d_in[6];
    const float* W3 = (const float*)d_in[7];
    const float* b3 = (const float*)d_in[8];
    float* out = (float*)d_out;

    const int n = in_sizes[0] / 128;       // 50000
    const int e = in_sizes[2];             // 640000
    const int* src = ei;
    const int* dst = ei + e;

    float *dinv, *nrm, *h, *agg, *h3;
    float *wf1h, *wf1l, *wf2h, *wf2l;
    cudaGetSymbolAddress((void**)&dinv, g_dinv);
    cudaGetSymbolAddress((void**)&nrm,  g_norm);
    cudaGetSymbolAddress((void**)&h,    g_h);
    cudaGetSymbolAddress((void**)&agg,  g_agg);
    cudaGetSymbolAddress((void**)&h3,   g_h3);
    cudaGetSymbolAddress((void**)&wf1h, g_wf1_hi);
    cudaGetSymbolAddress((void**)&wf1l, g_wf1_lo);
    cudaGetSymbolAddress((void**)&wf2h, g_wf2_hi);
    cudaGetSymbolAddress((void**)&wf2l, g_wf2_lo);

    const int nb_n = (n + 255) / 256;
    const int nb_e = (e + 255) / 256;

    // W fragment precompute (independent of graph preamble)
    wfrag_kernel<<<32, 256>>>(W1, wf1h, wf1l);
    wfrag_kernel<<<32, 256>>>(W2, wf2h, wf2l);

    // Degree + normalization
    deg_init_kernel<<<nb_n, 256>>>(dinv, n);
    deg_acc_kernel<<<nb_e, 256>>>(dst, ew, dinv, e);
    dinv_kernel<<<nb_n, 256>>>(dinv, n);
    norm_kernel<<<nb_e, 256>>>(src, dst, ew, dinv, nrm, e);

    const int gemm_blocks = (n + 127) / 128;
    const int scat_blocks = (e * 32 + 255) / 256;   // one warp per edge

    // Layer 1: h1 = x@W1 (tensor cores); agg init fused; edge scatter
    gemm128_tc<false><<<gemm_blocks, 256>>>(x, wf1h, wf1l, b1, dinv, h, agg, n);
    scatter128_kernel<<<scat_blocks, 256>>>(h, src, dst, nrm, agg, e);

    // Layer 2: relu fused into A load (in-place agg: safe, block-local rows)
    gemm128_tc<true><<<gemm_blocks, 256>>>(agg, wf2h, wf2l, b2, dinv, h, agg, n);
    scatter128_kernel<<<scat_blocks, 256>>>(h, src, dst, nrm, agg, e);

    // Layer 3: relu fused; output written directly to d_out
    static const int g40_smem = (64 * 129 + 128 * 40) * sizeof(float);
    cudaFuncSetAttribute(gemm40_kernel,
                         cudaFuncAttributeMaxDynamicSharedMemorySize, g40_smem);
    gemm40_kernel<<<(n + 63) / 64, 128, g40_smem>>>(agg, W3, b3, dinv, h3, out, n);

    long long s40_threads = (long long)e * 10;
    int s40_blocks = (int)((s40_threads + 255) / 256);
    scatter40_kernel<<<s40_blocks, 256>>>(h3, src, dst, nrm, out, e);
}